// round 16
// baseline (speedup 1.0000x reference)
#include <cuda_runtime.h>
#include <cuda_bf16.h>

// Fixed shapes: C=16, H=W=16, O=32, KH=KW=3, stride 1, pad 1
// d_out layout (float32):
//   [0:8192) x_out | [8192:16384) lb | [16384:24576) ub
//   [24576 : 24576+4096*8192) weights [4096,8192] | [33579008:33587200) bias_vec
// weights[(c,hi,wi),(o,y,x)] = K[o,c,hi-y+1,wi-x+1] iff |hi-y|<=1 && |wi-x|<=1 else 0.
//
// CONVERGED (best of 9 structural variants over 15 rounds):
//   - single merged launch: 4096 fill blocks + 32 conv blocks
//   - fill: one 32KB matrix row per 256-thread block, STG.256 (st.global.v8),
//     perfectly coalesced, band test k-invariant per thread
//   - workload is a 134MB output stream; measured plateau ~4.5TB/s effective
//     write throughput, path-independent (STG.128 == STG.256 == TMA bulk).
//   Kernel 29.3-29.7us (v8), no ncu pipe >50% -> L2/DRAM write wall.

#define OFF_LB   8192u
#define OFF_UB   16384u
#define OFF_W    24576u
#define OFF_BV   33579008u

#define CONV_BLOCKS 32
#define FILL_BLOCKS 4096            // one block per matrix row n
#define TOTAL_BLOCKS (CONV_BLOCKS + FILL_BLOCKS)

// 256-bit store (sm_100+ / PTX ISA 8.7+). p must be 32B-aligned.
__device__ __forceinline__ void stg256(float* p,
    float v0, float v1, float v2, float v3,
    float v4, float v5, float v6, float v7)
{
    asm volatile("st.global.v8.f32 [%0], {%1,%2,%3,%4,%5,%6,%7,%8};"
        :: "l"(p), "f"(v0), "f"(v1), "f"(v2), "f"(v3),
           "f"(v4), "f"(v5), "f"(v6), "f"(v7)
        : "memory");
}

__global__ void __launch_bounds__(256) dp_merged(
    const float* __restrict__ x,
    const float* __restrict__ lb,
    const float* __restrict__ ub,
    const float* __restrict__ kern,   // [32,16,3,3]
    const float* __restrict__ bias,   // [32]
    float* __restrict__ out)
{
    const int b = blockIdx.x;
    const int t = threadIdx.x;

    if (b >= CONV_BLOCKS) {
        // ------------------------------------------------------------------
        // FILL: block owns matrix row n (8192 floats = 1024 float8).
        // Thread t stores float8 j = t + k*256, k = 0..3 -> consecutive lanes
        // hit consecutive 32B chunks (2048B per warp-store, STG.256).
        // y=(t>>1)&15 and x0=8*(t&1) are k-invariant -> band test once per
        // thread; o = (t>>5) + 8k varies with k.
        // ------------------------------------------------------------------
        const unsigned n = (unsigned)(b - CONV_BLOCKS);   // 0..4095
        const int c  = (int)(n >> 8);
        const int hi = (int)((n >> 4) & 15u);
        const int wi = (int)(n & 15u);

        float* __restrict__ base = out + OFF_W + (size_t)n * 8192u + (unsigned)t * 8u;

        const int y  = (t >> 1) & 15;
        const int x0 = 8 * (t & 1);
        const int kh = hi - y + 1;                 // in-band iff 0..2
        const int d0 = wi - x0 + 1;                // kw for elem e = d0 - e

        if (((unsigned)kh < 3u) && (d0 >= 0) && (d0 <= 9)) {
            const int ob = t >> 5;                 // 0..7
            const int koff = c * 9 + kh * 3;
            #pragma unroll
            for (int k = 0; k < 4; ++k) {
                const int o = ob + 8 * k;
                const float* kb = kern + o * 144 + koff;
                float v[8];
                #pragma unroll
                for (int e = 0; e < 8; ++e) {
                    const int kw = d0 - e;
                    v[e] = ((unsigned)kw <= 2u) ? __ldg(kb + kw) : 0.f;
                }
                stg256(base + k * 2048, v[0], v[1], v[2], v[3], v[4], v[5], v[6], v[7]);
            }
        } else {
            #pragma unroll
            for (int k = 0; k < 4; ++k)
                stg256(base + k * 2048, 0.f, 0.f, 0.f, 0.f, 0.f, 0.f, 0.f, 0.f);
        }
        return;
    }

    // ----------------------------------------------------------------------
    // CONV: block b = output channel o; one thread per (y,x).
    // ----------------------------------------------------------------------
    __shared__ float sw[144];
    const int o = b;
    if (t < 144) sw[t] = kern[o * 144 + t];
    __syncthreads();

    const int y  = t >> 4;
    const int xx = t & 15;

    float xv = 0.f, lbv = 0.f, ubv = 0.f;

    #pragma unroll 4
    for (int c = 0; c < 16; ++c) {
        #pragma unroll
        for (int kh = 0; kh < 3; ++kh) {
            const int hi = y + kh - 1;
            if ((unsigned)hi >= 16u) continue;
            #pragma unroll
            for (int kw = 0; kw < 3; ++kw) {
                const int wi = xx + kw - 1;
                if ((unsigned)wi >= 16u) continue;
                const float w  = sw[c * 9 + kh * 3 + kw];
                const int   ii = c * 256 + hi * 16 + wi;
                const float xin = __ldg(x  + ii);
                const float lbi = __ldg(lb + ii);
                const float ubi = __ldg(ub + ii);
                xv += w * xin;
                if (w >= 0.f) { lbv += w * lbi; ubv += w * ubi; }
                else          { lbv += w * ubi; ubv += w * lbi; }
            }
        }
    }

    const float bv = __ldg(bias + o);
    const unsigned oi = (unsigned)(o * 256 + t);
    out[oi]           = xv  + bv;
    out[OFF_LB + oi]  = lbv + 3.f * bv;
    out[OFF_UB + oi]  = ubv + 3.f * bv;
    out[OFF_BV + oi]  = bv;
}

extern "C" void kernel_launch(void* const* d_in, const int* in_sizes, int n_in,
                              void* d_out, int out_size)
{
    const float* x    = (const float*)d_in[0];
    const float* lb   = (const float*)d_in[1];
    const float* ub   = (const float*)d_in[2];
    // d_in[3] = input_shape (int32) — compile-time constants
    const float* kern = (const float*)d_in[4];
    const float* bias = (const float*)d_in[5];
    float* out = (float*)d_out;

    dp_merged<<<TOTAL_BLOCKS, 256>>>(x, lb, ub, kern, bias, out);
}

// round 17
// speedup vs baseline: 1.0079x; 1.0079x over previous
#include <cuda_runtime.h>
#include <cuda_bf16.h>

// Fixed shapes: C=16, H=W=16, O=32, KH=KW=3, stride 1, pad 1
// d_out layout (float32):
//   [0:8192) x_out | [8192:16384) lb | [16384:24576) ub
//   [24576 : 24576+4096*8192) weights [4096,8192] | [33579008:33587200) bias_vec
// weights[(c,hi,wi),(o,y,x)] = K[o,c,hi-y+1,wi-x+1] iff |hi-y|<=1 && |wi-x|<=1 else 0.
//
// FINAL (best of 9 structural variants over 16 rounds; 3x reproduced):
//   - single merged launch: 4096 fill blocks + 32 conv blocks
//   - fill: one 32KB matrix row per 256-thread block, STG.256 (st.global.v8),
//     perfectly coalesced, band test k-invariant per thread
//   - workload is a 134MB output stream; measured plateau ~4.5TB/s effective
//     write throughput, path-independent (STG.128 == STG.256 == TMA bulk).
//   Kernel 29.3-30.2us, total 32.8us; no ncu pipe >50% -> L2/DRAM write wall.

#define OFF_LB   8192u
#define OFF_UB   16384u
#define OFF_W    24576u
#define OFF_BV   33579008u

#define CONV_BLOCKS 32
#define FILL_BLOCKS 4096            // one block per matrix row n
#define TOTAL_BLOCKS (CONV_BLOCKS + FILL_BLOCKS)

// 256-bit store (sm_100+ / PTX ISA 8.7+). p must be 32B-aligned.
__device__ __forceinline__ void stg256(float* p,
    float v0, float v1, float v2, float v3,
    float v4, float v5, float v6, float v7)
{
    asm volatile("st.global.v8.f32 [%0], {%1,%2,%3,%4,%5,%6,%7,%8};"
        :: "l"(p), "f"(v0), "f"(v1), "f"(v2), "f"(v3),
           "f"(v4), "f"(v5), "f"(v6), "f"(v7)
        : "memory");
}

__global__ void __launch_bounds__(256) dp_merged(
    const float* __restrict__ x,
    const float* __restrict__ lb,
    const float* __restrict__ ub,
    const float* __restrict__ kern,   // [32,16,3,3]
    const float* __restrict__ bias,   // [32]
    float* __restrict__ out)
{
    const int b = blockIdx.x;
    const int t = threadIdx.x;

    if (b >= CONV_BLOCKS) {
        // ------------------------------------------------------------------
        // FILL: block owns matrix row n (8192 floats = 1024 float8).
        // Thread t stores float8 j = t + k*256, k = 0..3 -> consecutive lanes
        // hit consecutive 32B chunks (2048B per warp-store, STG.256).
        // y=(t>>1)&15 and x0=8*(t&1) are k-invariant -> band test once per
        // thread; o = (t>>5) + 8k varies with k.
        // ------------------------------------------------------------------
        const unsigned n = (unsigned)(b - CONV_BLOCKS);   // 0..4095
        const int c  = (int)(n >> 8);
        const int hi = (int)((n >> 4) & 15u);
        const int wi = (int)(n & 15u);

        float* __restrict__ base = out + OFF_W + (size_t)n * 8192u + (unsigned)t * 8u;

        const int y  = (t >> 1) & 15;
        const int x0 = 8 * (t & 1);
        const int kh = hi - y + 1;                 // in-band iff 0..2
        const int d0 = wi - x0 + 1;                // kw for elem e = d0 - e

        if (((unsigned)kh < 3u) && (d0 >= 0) && (d0 <= 9)) {
            const int ob = t >> 5;                 // 0..7
            const int koff = c * 9 + kh * 3;
            #pragma unroll
            for (int k = 0; k < 4; ++k) {
                const int o = ob + 8 * k;
                const float* kb = kern + o * 144 + koff;
                float v[8];
                #pragma unroll
                for (int e = 0; e < 8; ++e) {
                    const int kw = d0 - e;
                    v[e] = ((unsigned)kw <= 2u) ? __ldg(kb + kw) : 0.f;
                }
                stg256(base + k * 2048, v[0], v[1], v[2], v[3], v[4], v[5], v[6], v[7]);
            }
        } else {
            #pragma unroll
            for (int k = 0; k < 4; ++k)
                stg256(base + k * 2048, 0.f, 0.f, 0.f, 0.f, 0.f, 0.f, 0.f, 0.f);
        }
        return;
    }

    // ----------------------------------------------------------------------
    // CONV: block b = output channel o; one thread per (y,x).
    // ----------------------------------------------------------------------
    __shared__ float sw[144];
    const int o = b;
    if (t < 144) sw[t] = kern[o * 144 + t];
    __syncthreads();

    const int y  = t >> 4;
    const int xx = t & 15;

    float xv = 0.f, lbv = 0.f, ubv = 0.f;

    #pragma unroll 4
    for (int c = 0; c < 16; ++c) {
        #pragma unroll
        for (int kh = 0; kh < 3; ++kh) {
            const int hi = y + kh - 1;
            if ((unsigned)hi >= 16u) continue;
            #pragma unroll
            for (int kw = 0; kw < 3; ++kw) {
                const int wi = xx + kw - 1;
                if ((unsigned)wi >= 16u) continue;
                const float w  = sw[c * 9 + kh * 3 + kw];
                const int   ii = c * 256 + hi * 16 + wi;
                const float xin = __ldg(x  + ii);
                const float lbi = __ldg(lb + ii);
                const float ubi = __ldg(ub + ii);
                xv += w * xin;
                if (w >= 0.f) { lbv += w * lbi; ubv += w * ubi; }
                else          { lbv += w * ubi; ubv += w * lbi; }
            }
        }
    }

    const float bv = __ldg(bias + o);
    const unsigned oi = (unsigned)(o * 256 + t);
    out[oi]           = xv  + bv;
    out[OFF_LB + oi]  = lbv + 3.f * bv;
    out[OFF_UB + oi]  = ubv + 3.f * bv;
    out[OFF_BV + oi]  = bv;
}

extern "C" void kernel_launch(void* const* d_in, const int* in_sizes, int n_in,
                              void* d_out, int out_size)
{
    const float* x    = (const float*)d_in[0];
    const float* lb   = (const float*)d_in[1];
    const float* ub   = (const float*)d_in[2];
    // d_in[3] = input_shape (int32) — compile-time constants
    const float* kern = (const float*)d_in[4];
    const float* bias = (const float*)d_in[5];
    float* out = (float*)d_out;

    dp_merged<<<TOTAL_BLOCKS, 256>>>(x, lb, ub, kern, bias, out);
}